// round 6
// baseline (speedup 1.0000x reference)
#include <cuda_runtime.h>
#include <cuda_bf16.h>
#include <cstdint>

// Problem dims (fixed)
#define B_   4
#define T_   2048
#define D_   2048
#define H_   8
#define DK_  256
#define M_   64
#define HM_  512              // H_*M_
#define BT_  8192             // B_*T_

// ---------------------------------------------------------------------------
// Scratch (device globals; no allocation allowed)
// ---------------------------------------------------------------------------
__device__ float g_xn[16777216];  // normalized x   [BT, D]
__device__ float g_q [16777216];  // swish(q)       [BT, D]
__device__ float g_k [16777216];  // swish(k)       [BT, D]
__device__ float g_v [16777216];  // swish(v)       [BT, D]
__device__ float g_gl[ 4194304];  // log gates g    [BT, HM]
__device__ float g_sl[ 4194304];  // s = 1-exp(g)   [BT, HM]
__device__ float g_o [16777216];  // scan output    [BT, D]
__device__ float g_o2[16777216];  // post g-norm    [BT, D]

__device__ __forceinline__ float swishf(float x) { return x / (1.0f + expf(-x)); }

// ---------------------------------------------------------------------------
// RMSNorm over last dim (D=2048). One block per row, 256 threads, 8 elems/thr.
// ---------------------------------------------------------------------------
__global__ __launch_bounds__(256)
void rmsnorm_kernel(const float* __restrict__ x, const float* __restrict__ w,
                    float* __restrict__ y)
{
    const int row = blockIdx.x;
    const int t = threadIdx.x;
    const float4* xr = reinterpret_cast<const float4*>(x) + (size_t)row * (D_ / 4);
    float4 v0 = xr[t];
    float4 v1 = xr[t + 256];
    float ss = v0.x*v0.x + v0.y*v0.y + v0.z*v0.z + v0.w*v0.w
             + v1.x*v1.x + v1.y*v1.y + v1.z*v1.z + v1.w*v1.w;
#pragma unroll
    for (int o = 16; o; o >>= 1) ss += __shfl_xor_sync(0xffffffffu, ss, o);
    __shared__ float red[8];
    if ((t & 31) == 0) red[t >> 5] = ss;
    __syncthreads();
    float tot = red[0]+red[1]+red[2]+red[3]+red[4]+red[5]+red[6]+red[7];
    const float sc = rsqrtf(tot * (1.0f / (float)D_) + 1e-5f);
    const float4* wr = reinterpret_cast<const float4*>(w);
    float4 w0 = wr[t], w1 = wr[t + 256];
    float4 r0, r1;
    r0.x = v0.x * sc * w0.x;  r0.y = v0.y * sc * w0.y;
    r0.z = v0.z * sc * w0.z;  r0.w = v0.w * sc * w0.w;
    r1.x = v1.x * sc * w1.x;  r1.y = v1.y * sc * w1.y;
    r1.z = v1.z * sc * w1.z;  r1.w = v1.w * sc * w1.w;
    float4* yr = reinterpret_cast<float4*>(y) + (size_t)row * (D_ / 4);
    yr[t] = r0;
    yr[t + 256] = r1;
}

// ---------------------------------------------------------------------------
// swish then RMSNorm (output path): y = rmsnorm(swish(x)) * w
// ---------------------------------------------------------------------------
__global__ __launch_bounds__(256)
void swishrms_kernel(const float* __restrict__ x, const float* __restrict__ w,
                     float* __restrict__ y)
{
    const int row = blockIdx.x;
    const int t = threadIdx.x;
    const float4* xr = reinterpret_cast<const float4*>(x) + (size_t)row * (D_ / 4);
    float4 v0 = xr[t];
    float4 v1 = xr[t + 256];
    v0.x = swishf(v0.x); v0.y = swishf(v0.y); v0.z = swishf(v0.z); v0.w = swishf(v0.w);
    v1.x = swishf(v1.x); v1.y = swishf(v1.y); v1.z = swishf(v1.z); v1.w = swishf(v1.w);
    float ss = v0.x*v0.x + v0.y*v0.y + v0.z*v0.z + v0.w*v0.w
             + v1.x*v1.x + v1.y*v1.y + v1.z*v1.z + v1.w*v1.w;
#pragma unroll
    for (int o = 16; o; o >>= 1) ss += __shfl_xor_sync(0xffffffffu, ss, o);
    __shared__ float red[8];
    if ((t & 31) == 0) red[t >> 5] = ss;
    __syncthreads();
    float tot = red[0]+red[1]+red[2]+red[3]+red[4]+red[5]+red[6]+red[7];
    const float sc = rsqrtf(tot * (1.0f / (float)D_) + 1e-5f);
    const float4* wr = reinterpret_cast<const float4*>(w);
    float4 w0 = wr[t], w1 = wr[t + 256];
    float4 r0, r1;
    r0.x = v0.x * sc * w0.x;  r0.y = v0.y * sc * w0.y;
    r0.z = v0.z * sc * w0.z;  r0.w = v0.w * sc * w0.w;
    r1.x = v1.x * sc * w1.x;  r1.y = v1.y * sc * w1.y;
    r1.z = v1.z * sc * w1.z;  r1.w = v1.w * sc * w1.w;
    float4* yr = reinterpret_cast<float4*>(y) + (size_t)row * (D_ / 4);
    yr[t] = r0;
    yr[t + 256] = r1;
}

// ---------------------------------------------------------------------------
// SGEMM (NT): C[m, n] = sum_k A[m, k] * Bw[n, k]   (einsum 'btd,kd->btk')
// 128x128 block tile, BK=8, 256 threads, 8x8 per thread, double-buffered smem.
// MODE 0: swish epilogue (q/k/v).  MODE 1: gate epilogue (writes g to C,
// s=1-exp(g) to C2).  MODE 2: plain (final projection).
// ---------------------------------------------------------------------------
template<int MODE>
__global__ __launch_bounds__(256, 2)
void sgemm_nt(const float* __restrict__ A, const float* __restrict__ Bw,
              float* __restrict__ C, float* __restrict__ C2,
              const int K, const int ldc)
{
    __shared__ float As[2][8][132];
    __shared__ float Bs[2][8][132];

    const int tid  = threadIdx.x;
    const int m0   = blockIdx.y * 128;
    const int n0   = blockIdx.x * 128;
    const int tm   = (tid >> 4) << 3;   // 0..120
    const int tn   = (tid & 15) << 3;   // 0..120
    const int lrow = tid >> 1;          // 0..127
    const int lk   = (tid & 1) << 2;    // 0 or 4

    const float* Ap = A  + (size_t)(m0 + lrow) * K + lk;
    const float* Bp = Bw + (size_t)(n0 + lrow) * K + lk;

    float acc[8][8];
#pragma unroll
    for (int i = 0; i < 8; i++)
#pragma unroll
        for (int j = 0; j < 8; j++) acc[i][j] = 0.0f;

    {   // prologue: tile 0
        float4 a4 = *reinterpret_cast<const float4*>(Ap);
        float4 b4 = *reinterpret_cast<const float4*>(Bp);
        As[0][lk+0][lrow] = a4.x; As[0][lk+1][lrow] = a4.y;
        As[0][lk+2][lrow] = a4.z; As[0][lk+3][lrow] = a4.w;
        Bs[0][lk+0][lrow] = b4.x; Bs[0][lk+1][lrow] = b4.y;
        Bs[0][lk+2][lrow] = b4.z; Bs[0][lk+3][lrow] = b4.w;
    }
    __syncthreads();

    const int nkt = K >> 3;
    for (int kt = 0; kt < nkt; kt++) {
        const int cur = kt & 1;
        float4 a4, b4;
        const bool pf = (kt + 1 < nkt);
        if (pf) {
            a4 = *reinterpret_cast<const float4*>(Ap + ((size_t)(kt + 1) << 3));
            b4 = *reinterpret_cast<const float4*>(Bp + ((size_t)(kt + 1) << 3));
        }
#pragma unroll
        for (int kk = 0; kk < 8; kk++) {
            float4 af0 = *reinterpret_cast<const float4*>(&As[cur][kk][tm]);
            float4 af1 = *reinterpret_cast<const float4*>(&As[cur][kk][tm + 4]);
            float4 bf0 = *reinterpret_cast<const float4*>(&Bs[cur][kk][tn]);
            float4 bf1 = *reinterpret_cast<const float4*>(&Bs[cur][kk][tn + 4]);
            float a[8] = {af0.x, af0.y, af0.z, af0.w, af1.x, af1.y, af1.z, af1.w};
            float b[8] = {bf0.x, bf0.y, bf0.z, bf0.w, bf1.x, bf1.y, bf1.z, bf1.w};
#pragma unroll
            for (int i = 0; i < 8; i++)
#pragma unroll
                for (int j = 0; j < 8; j++)
                    acc[i][j] += a[i] * b[j];
        }
        if (pf) {
            const int nb = cur ^ 1;
            As[nb][lk+0][lrow] = a4.x; As[nb][lk+1][lrow] = a4.y;
            As[nb][lk+2][lrow] = a4.z; As[nb][lk+3][lrow] = a4.w;
            Bs[nb][lk+0][lrow] = b4.x; Bs[nb][lk+1][lrow] = b4.y;
            Bs[nb][lk+2][lrow] = b4.z; Bs[nb][lk+3][lrow] = b4.w;
        }
        __syncthreads();
    }

    // epilogue
#pragma unroll
    for (int i = 0; i < 8; i++) {
        const size_t ro = (size_t)(m0 + tm + i) * ldc + (size_t)(n0 + tn);
        if (MODE == 1) {
            float gv[8], sv[8];
#pragma unroll
            for (int j = 0; j < 8; j++) {
                float c  = acc[i][j];
                // stable log_sigmoid: min(x,0) - log1p(exp(-|x|))
                float ls = fminf(c, 0.0f) - log1pf(expf(-fabsf(c)));
                float gg = ls * 0.125f;           // / GLN (=8)
                gv[j] = gg;
                sv[j] = -expm1f(gg);              // 1 - exp(g)
            }
            *reinterpret_cast<float4*>(C  + ro)     = make_float4(gv[0], gv[1], gv[2], gv[3]);
            *reinterpret_cast<float4*>(C  + ro + 4) = make_float4(gv[4], gv[5], gv[6], gv[7]);
            *reinterpret_cast<float4*>(C2 + ro)     = make_float4(sv[0], sv[1], sv[2], sv[3]);
            *reinterpret_cast<float4*>(C2 + ro + 4) = make_float4(sv[4], sv[5], sv[6], sv[7]);
        } else {
            float r[8];
#pragma unroll
            for (int j = 0; j < 8; j++) {
                float c = acc[i][j];
                r[j] = (MODE == 0) ? swishf(c) : c;
            }
            *reinterpret_cast<float4*>(C + ro)     = make_float4(r[0], r[1], r[2], r[3]);
            *reinterpret_cast<float4*>(C + ro + 4) = make_float4(r[4], r[5], r[6], r[7]);
        }
    }
}

// ---------------------------------------------------------------------------
// Sequential GSA scan. One CTA per (b,h). 256 threads.
// State register-resident:
//   Hk^T: warp w owns slots m = 8w..8w+7; lane l owns dk = 8l..8l+7
//         -> hk[mi][di] = Hk[dk = 8l+di][m = 8w+mi]            (64 regs)
//   Hv:   thread tid owns dv = tid -> hv[m] = Hv[m][tid]        (64 regs)
// Per step: update Hk + fused q-dot (warp shfl reduce) -> o1[64];
// softmax (warp 0); update Hv + fused qv-dot -> o[dv].
// Inputs for t+1 prefetched into registers during step t.
// ---------------------------------------------------------------------------
__global__ __launch_bounds__(256, 1)
void gsa_scan_kernel(const float* __restrict__ Q, const float* __restrict__ Kq,
                     const float* __restrict__ V, const float* __restrict__ S,
                     const float* __restrict__ G, float* __restrict__ O)
{
    const int bh   = blockIdx.x;
    const int b    = bh >> 3;
    const int h    = bh & 7;
    const int tid  = threadIdx.x;
    const int lane = tid & 31;
    const int w    = tid >> 5;

    __shared__ __align__(16) float sq[256], sk[256], sv[256];
    __shared__ __align__(16) float sdec[64], ssl[64], so1[64], sqv[64];

    const size_t qbase = (size_t)b * T_ * D_  + (size_t)h * DK_ + tid;  // stride D_ per t
    const size_t fbase = (size_t)b * T_ * HM_ + (size_t)h * M_  + tid;  // stride HM_ per t (tid<64)

    float hk[8][8];
    float hv[64];
#pragma unroll
    for (int mi = 0; mi < 8; mi++)
#pragma unroll
        for (int di = 0; di < 8; di++) hk[mi][di] = 0.0f;
#pragma unroll
    for (int m = 0; m < 64; m++) hv[m] = 0.0f;

    // initial loads (t = 0)
    float nq = Q[qbase], nk = Kq[qbase], nv = V[qbase];
    float nsv = 0.0f, ngv = 0.0f;
    if (tid < 64) { nsv = S[fbase]; ngv = G[fbase]; }

    for (int t = 0; t < T_; t++) {
        // commit step-t inputs to shared
        sq[tid] = nq; sk[tid] = nk; sv[tid] = nv;
        if (tid < 64) { ssl[tid] = nsv; sdec[tid] = expf(ngv); }
        __syncthreads();                                   // A

        // prefetch t+1 (clamped; redundant last load is harmless)
        {
            const int tn_ = (t + 1 < T_) ? (t + 1) : t;
            nq = Q [qbase + (size_t)tn_ * D_];
            nk = Kq[qbase + (size_t)tn_ * D_];
            nv = V [qbase + (size_t)tn_ * D_];
            if (tid < 64) {
                nsv = S[fbase + (size_t)tn_ * HM_];
                ngv = G[fbase + (size_t)tn_ * HM_];
            }
        }

        // ---- pass 1: Hk update + o1 = q . Hk ----
        float4 qa = *reinterpret_cast<const float4*>(&sq[lane * 8]);
        float4 qb = reinterpret_cast<const float4*>(&sq[lane * 8])[1];
        float4 ka = *reinterpret_cast<const float4*>(&sk[lane * 8]);
        float4 kb = reinterpret_cast<const float4*>(&sk[lane * 8])[1];
        float qr[8] = {qa.x, qa.y, qa.z, qa.w, qb.x, qb.y, qb.z, qb.w};
        float kr[8] = {ka.x, ka.y, ka.z, ka.w, kb.x, kb.y, kb.z, kb.w};

#pragma unroll
        for (int mi = 0; mi < 8; mi++) {
            const int m = w * 8 + mi;
            const float dm = sdec[m];
            const float sm = ssl[m];
            float p = 0.0f;
#pragma unroll
            for (int di = 0; di < 8; di++) {
                hk[mi][di] = hk[mi][di] * dm + kr[di] * sm;
                p += qr[di] * hk[mi][di];
            }
            p += __shfl_xor_sync(0xffffffffu, p, 16);
            p += __shfl_xor_sync(0xffffffffu, p, 8);
            p += __shfl_xor_sync(0xffffffffu, p, 4);
            p += __shfl_xor_sync(0xffffffffu, p, 2);
            p += __shfl_xor_sync(0xffffffffu, p, 1);
            if (lane == mi) so1[m] = p;                    // SCALE = 1.0
        }
        __syncthreads();                                   // B

        // ---- softmax over 64 slots (warp 0) ----
        if (w == 0) {
            float a = so1[lane], c = so1[lane + 32];
            float mx = fmaxf(a, c);
#pragma unroll
            for (int o = 16; o; o >>= 1) mx = fmaxf(mx, __shfl_xor_sync(0xffffffffu, mx, o));
            float ea = expf(a - mx), ec = expf(c - mx);
            float sm_ = ea + ec;
#pragma unroll
            for (int o = 16; o; o >>= 1) sm_ += __shfl_xor_sync(0xffffffffu, sm_, o);
            const float inv = 1.0f / sm_;
            sqv[lane]      = ea * inv;
            sqv[lane + 32] = ec * inv;
        }
        __syncthreads();                                   // C

        // ---- pass 2: Hv update + o = qv . Hv ----
        const float vo = sv[tid];
        float acc = 0.0f;
#pragma unroll
        for (int m = 0; m < 64; m++) {
            hv[m] = hv[m] * sdec[m] + ssl[m] * vo;
            acc += sqv[m] * hv[m];
        }
        O[qbase + (size_t)t * D_] = acc;
        __syncthreads();                                   // D
    }
}

// ---------------------------------------------------------------------------
// Host launcher
// ---------------------------------------------------------------------------
extern "C" void kernel_launch(void* const* d_in, const int* in_sizes, int n_in,
                              void* d_out, int out_size)
{
    (void)in_sizes; (void)n_in; (void)out_size;
    const float* hs       = (const float*)d_in[0];
    const float* norm_w   = (const float*)d_in[1];
    const float* q_w      = (const float*)d_in[2];
    const float* k_w      = (const float*)d_in[3];
    const float* v_w      = (const float*)d_in[4];
    const float* f_w      = (const float*)d_in[5];
    const float* g_norm_w = (const float*)d_in[6];
    const float* o_w      = (const float*)d_in[7];

    float *xn, *q, *k, *v, *gl, *sl, *o, *o2;
    cudaGetSymbolAddress((void**)&xn, g_xn);
    cudaGetSymbolAddress((void**)&q,  g_q);
    cudaGetSymbolAddress((void**)&k,  g_k);
    cudaGetSymbolAddress((void**)&v,  g_v);
    cudaGetSymbolAddress((void**)&gl, g_gl);
    cudaGetSymbolAddress((void**)&sl, g_sl);
    cudaGetSymbolAddress((void**)&o,  g_o);
    cudaGetSymbolAddress((void**)&o2, g_o2);

    // 1) x = rmsnorm(hidden_states) * norm_w
    rmsnorm_kernel<<<BT_, 256>>>(hs, norm_w, xn);

    // 2) projections (fused activations in epilogue)
    dim3 gqkv(D_ / 128, BT_ / 128);       // (16, 64)
    sgemm_nt<0><<<gqkv, 256>>>(xn, q_w, q, nullptr, D_, D_);
    sgemm_nt<0><<<gqkv, 256>>>(xn, k_w, k, nullptr, D_, D_);
    sgemm_nt<0><<<gqkv, 256>>>(xn, v_w, v, nullptr, D_, D_);
    dim3 gf(HM_ / 128, BT_ / 128);        // (4, 64)
    sgemm_nt<1><<<gf, 256>>>(xn, f_w, gl, sl, D_, HM_);

    // 3) sequential gated slot attention scan
    gsa_scan_kernel<<<B_ * H_, 256>>>(q, k, v, sl, gl, o);

    // 4) o = rmsnorm(swish(o)) * g_norm_w
    swishrms_kernel<<<BT_, 256>>>(o, g_norm_w, o2);

    // 5) final projection -> d_out (fp32)
    sgemm_nt<2><<<gqkv, 256>>>(o2, o_w, (float*)d_out, nullptr, D_, D_);
}

// round 8
// speedup vs baseline: 1.5447x; 1.5447x over previous
#include <cuda_runtime.h>
#include <cuda_bf16.h>
#include <cstdint>

// Problem dims (fixed)
#define B_   4
#define T_   2048
#define D_   2048
#define H_   8
#define DK_  256
#define M_   64
#define HM_  512              // H_*M_
#define BT_  8192             // B_*T_

// ---------------------------------------------------------------------------
// Scratch (device globals; no allocation allowed)
// ---------------------------------------------------------------------------
__device__ float g_q [16777216];  // swish(q)       [BT, D]
__device__ float g_k [16777216];  // swish(k)       [BT, D]
__device__ float g_v [16777216];  // swish(v)       [BT, D]
__device__ float g_gl[ 4194304];  // log gates g    [BT, HM]
__device__ float g_sl[ 4194304];  // s = 1-exp(g)   [BT, HM]
__device__ float g_o [16777216];  // scan output    [BT, D]

// bf16 split buffers
__device__ __nv_bfloat16 g_xh [16777216], g_xl [16777216];  // activations hi/lo
__device__ __nv_bfloat16 g_qwh[ 4194304], g_qwl[ 4194304];
__device__ __nv_bfloat16 g_kwh[ 4194304], g_kwl[ 4194304];
__device__ __nv_bfloat16 g_vwh[ 4194304], g_vwl[ 4194304];
__device__ __nv_bfloat16 g_owh[ 4194304], g_owl[ 4194304];
__device__ __nv_bfloat16 g_fwh[ 1048576], g_fwl[ 1048576];

__device__ __forceinline__ float swishf(float x) { return x / (1.0f + expf(-x)); }

// split fp32 -> (hi, lo) bf16
__device__ __forceinline__ void split1(float x, __nv_bfloat16& h, __nv_bfloat16& l)
{
    __nv_bfloat16 hh = __float2bfloat16(x);
    h = hh;
    l = __float2bfloat16(x - __bfloat162float(hh));
}

__device__ __forceinline__ void split4(float4 v, __nv_bfloat16* hp, __nv_bfloat16* lp)
{
    __nv_bfloat16 h0,h1,h2,h3,l0,l1,l2,l3;
    split1(v.x,h0,l0); split1(v.y,h1,l1); split1(v.z,h2,l2); split1(v.w,h3,l3);
    __nv_bfloat162* hp2 = reinterpret_cast<__nv_bfloat162*>(hp);
    __nv_bfloat162* lp2 = reinterpret_cast<__nv_bfloat162*>(lp);
    hp2[0] = __nv_bfloat162(h0,h1); hp2[1] = __nv_bfloat162(h2,h3);
    lp2[0] = __nv_bfloat162(l0,l1); lp2[1] = __nv_bfloat162(l2,l3);
}

// ---------------------------------------------------------------------------
// Weight splitter: fp32 -> bf16 hi/lo. 4 elems/thread.
// ---------------------------------------------------------------------------
__global__ __launch_bounds__(256)
void splitw_kernel(const float* __restrict__ x, __nv_bfloat16* __restrict__ h,
                   __nv_bfloat16* __restrict__ l)
{
    const int i = (blockIdx.x * 256 + threadIdx.x) * 4;
    float4 v = *reinterpret_cast<const float4*>(x + i);
    split4(v, h + i, l + i);
}

// ---------------------------------------------------------------------------
// RMSNorm over last dim (D=2048), output split bf16 hi/lo.
// One block per row, 256 threads, 8 elems/thr.
// ---------------------------------------------------------------------------
__global__ __launch_bounds__(256)
void rmsnorm_split_kernel(const float* __restrict__ x, const float* __restrict__ w,
                          __nv_bfloat16* __restrict__ yh, __nv_bfloat16* __restrict__ yl)
{
    const int row = blockIdx.x;
    const int t = threadIdx.x;
    const float4* xr = reinterpret_cast<const float4*>(x) + (size_t)row * (D_ / 4);
    float4 v0 = xr[t];
    float4 v1 = xr[t + 256];
    float ss = v0.x*v0.x + v0.y*v0.y + v0.z*v0.z + v0.w*v0.w
             + v1.x*v1.x + v1.y*v1.y + v1.z*v1.z + v1.w*v1.w;
#pragma unroll
    for (int o = 16; o; o >>= 1) ss += __shfl_xor_sync(0xffffffffu, ss, o);
    __shared__ float red[8];
    if ((t & 31) == 0) red[t >> 5] = ss;
    __syncthreads();
    float tot = red[0]+red[1]+red[2]+red[3]+red[4]+red[5]+red[6]+red[7];
    const float sc = rsqrtf(tot * (1.0f / (float)D_) + 1e-5f);
    const float4* wr = reinterpret_cast<const float4*>(w);
    float4 w0 = wr[t], w1 = wr[t + 256];
    float4 r0, r1;
    r0.x = v0.x * sc * w0.x;  r0.y = v0.y * sc * w0.y;
    r0.z = v0.z * sc * w0.z;  r0.w = v0.w * sc * w0.w;
    r1.x = v1.x * sc * w1.x;  r1.y = v1.y * sc * w1.y;
    r1.z = v1.z * sc * w1.z;  r1.w = v1.w * sc * w1.w;
    const size_t base = (size_t)row * D_;
    split4(r0, yh + base + t * 4,        yl + base + t * 4);
    split4(r1, yh + base + (t + 256)*4,  yl + base + (t + 256)*4);
}

// ---------------------------------------------------------------------------
// swish then RMSNorm, output split bf16 hi/lo.
// ---------------------------------------------------------------------------
__global__ __launch_bounds__(256)
void swishrms_split_kernel(const float* __restrict__ x, const float* __restrict__ w,
                           __nv_bfloat16* __restrict__ yh, __nv_bfloat16* __restrict__ yl)
{
    const int row = blockIdx.x;
    const int t = threadIdx.x;
    const float4* xr = reinterpret_cast<const float4*>(x) + (size_t)row * (D_ / 4);
    float4 v0 = xr[t];
    float4 v1 = xr[t + 256];
    v0.x = swishf(v0.x); v0.y = swishf(v0.y); v0.z = swishf(v0.z); v0.w = swishf(v0.w);
    v1.x = swishf(v1.x); v1.y = swishf(v1.y); v1.z = swishf(v1.z); v1.w = swishf(v1.w);
    float ss = v0.x*v0.x + v0.y*v0.y + v0.z*v0.z + v0.w*v0.w
             + v1.x*v1.x + v1.y*v1.y + v1.z*v1.z + v1.w*v1.w;
#pragma unroll
    for (int o = 16; o; o >>= 1) ss += __shfl_xor_sync(0xffffffffu, ss, o);
    __shared__ float red[8];
    if ((t & 31) == 0) red[t >> 5] = ss;
    __syncthreads();
    float tot = red[0]+red[1]+red[2]+red[3]+red[4]+red[5]+red[6]+red[7];
    const float sc = rsqrtf(tot * (1.0f / (float)D_) + 1e-5f);
    const float4* wr = reinterpret_cast<const float4*>(w);
    float4 w0 = wr[t], w1 = wr[t + 256];
    float4 r0, r1;
    r0.x = v0.x * sc * w0.x;  r0.y = v0.y * sc * w0.y;
    r0.z = v0.z * sc * w0.z;  r0.w = v0.w * sc * w0.w;
    r1.x = v1.x * sc * w1.x;  r1.y = v1.y * sc * w1.y;
    r1.z = v1.z * sc * w1.z;  r1.w = v1.w * sc * w1.w;
    const size_t base = (size_t)row * D_;
    split4(r0, yh + base + t * 4,        yl + base + t * 4);
    split4(r1, yh + base + (t + 256)*4,  yl + base + (t + 256)*4);
}

// ---------------------------------------------------------------------------
// PTX wrappers
// ---------------------------------------------------------------------------
__device__ __forceinline__ void mma_bf16(float* d, const uint32_t* a, const uint32_t* b)
{
    asm volatile(
        "mma.sync.aligned.m16n8k16.row.col.f32.bf16.bf16.f32 "
        "{%0,%1,%2,%3}, {%4,%5,%6,%7}, {%8,%9}, {%0,%1,%2,%3};"
        : "+f"(d[0]), "+f"(d[1]), "+f"(d[2]), "+f"(d[3])
        : "r"(a[0]), "r"(a[1]), "r"(a[2]), "r"(a[3]), "r"(b[0]), "r"(b[1]));
}

__device__ __forceinline__ void ldsm4(uint32_t* r, uint32_t addr)
{
    asm volatile("ldmatrix.sync.aligned.m8n8.x4.shared.b16 {%0,%1,%2,%3}, [%4];"
                 : "=r"(r[0]), "=r"(r[1]), "=r"(r[2]), "=r"(r[3]) : "r"(addr));
}

__device__ __forceinline__ void cp16(uint32_t dst, const void* src)
{
    asm volatile("cp.async.cg.shared.global [%0], [%1], 16;" :: "r"(dst), "l"(src));
}
__device__ __forceinline__ void cp_commit() { asm volatile("cp.async.commit_group;"); }
template<int N> __device__ __forceinline__ void cp_wait()
{ asm volatile("cp.async.wait_group %0;" :: "n"(N)); }

// ---------------------------------------------------------------------------
// Split-bf16 GEMM (NT): C[m,n] = sum_k A[m,k]*Bw[n,k],
// C ~= Ah*Bh + Ah*Bl + Al*Bh  (fp32 accumulate).
// 128x128 tile, BK=32, 256 threads, mma.m16n8k16, cp.async double buffer.
// Smem tile rows padded to 40 bf16 (80B) -> conflict-free ldmatrix.
// MODE 0: swish epilogue. MODE 1: gate epilogue (C=g, C2=s). MODE 2: plain.
// ---------------------------------------------------------------------------
#define TILE_B   10240            // one 128x40 bf16 tile in bytes
#define STAGE_B  (4 * TILE_B)     // Ah, Al, Bh, Bl
#define SMEM_B   (2 * STAGE_B)    // double buffered (81920 B)

template<int MODE>
__global__ __launch_bounds__(256, 1)
void bgemm_nt(const __nv_bfloat16* __restrict__ Ah, const __nv_bfloat16* __restrict__ Al,
              const __nv_bfloat16* __restrict__ Bh, const __nv_bfloat16* __restrict__ Bl,
              float* __restrict__ C, float* __restrict__ C2,
              const int K, const int ldc)
{
    extern __shared__ __align__(16) char smem_raw[];
    const uint32_t sbase = (uint32_t)__cvta_generic_to_shared(smem_raw);

    const int tid    = threadIdx.x;
    const int lane   = tid & 31;
    const int warp   = tid >> 5;
    const int warp_m = warp >> 1;         // 0..3 -> 32 rows each
    const int warp_n = warp & 1;          // 0..1 -> 64 cols each
    const int m0     = blockIdx.y * 128;
    const int n0     = blockIdx.x * 128;

    const int lrow = tid >> 2;            // 0..63  (loader: not used directly)
    (void)lrow;

    float acc[2][8][4];
#pragma unroll
    for (int mi = 0; mi < 2; mi++)
#pragma unroll
        for (int ni = 0; ni < 8; ni++)
#pragma unroll
            for (int e = 0; e < 4; e++) acc[mi][ni][e] = 0.0f;

    // --- loader lambda (manual): stage s, k-tile kt ---
    // 4 tiles x 128 rows x 4 chunks(16B) = 2048 chunks per tile-set? No:
    // per tile: 128 rows x 2 chunks? 32 bf16/row = 64B = 4 chunks of 16B.
    // 128*4 = 512 chunks / 256 thr = 2 per thread per tile.
    auto load_stage = [&](int s, int kt) {
        const uint32_t sb = sbase + s * STAGE_B;
        const int k0 = kt * 32;
#pragma unroll
        for (int i = 0; i < 2; i++) {
            const int c   = tid + (i << 8);
            const int row = c >> 2;
            const int kc  = (c & 3) << 3;               // bf16 elems
            const uint32_t doff = sb + (uint32_t)(row * 40 + kc) * 2;
            const size_t gA = (size_t)(m0 + row) * K + k0 + kc;
            const size_t gB = (size_t)(n0 + row) * K + k0 + kc;
            cp16(doff,               Ah + gA);
            cp16(doff + TILE_B,      Al + gA);
            cp16(doff + 2 * TILE_B,  Bh + gB);
            cp16(doff + 3 * TILE_B,  Bl + gB);
        }
    };

    load_stage(0, 0);
    cp_commit();

    const int nkt = K >> 5;
    const int r = lane & 7;
    const int g = lane >> 3;
    const int a_row_off = ((g & 1) << 3) + r;
    const int a_k_off   = (g >> 1) << 3;
    const int b_row_off = ((g >> 1) << 3) + r;
    const int b_k_off   = (g & 1) << 3;

    for (int kt = 0; kt < nkt; kt++) {
        if (kt + 1 < nkt) { load_stage((kt + 1) & 1, kt + 1); cp_commit(); cp_wait<1>(); }
        else              { cp_wait<0>(); }
        __syncthreads();

        const uint32_t sA = sbase + (kt & 1) * STAGE_B;
        const uint32_t sB = sA + 2 * TILE_B;

#pragma unroll
        for (int kk = 0; kk < 32; kk += 16) {
            uint32_t ah[2][4], al[2][4], bh[8][2], bl[8][2];
#pragma unroll
            for (int mi = 0; mi < 2; mi++) {
                const uint32_t addr = sA +
                    (uint32_t)(((warp_m << 5) + (mi << 4) + a_row_off) * 40 + kk + a_k_off) * 2;
                ldsm4(ah[mi], addr);
                ldsm4(al[mi], addr + TILE_B);
            }
#pragma unroll
            for (int p = 0; p < 4; p++) {
                const uint32_t addr = sB +
                    (uint32_t)(((warp_n << 6) + (p << 4) + b_row_off) * 40 + kk + b_k_off) * 2;
                uint32_t t4[4];
                ldsm4(t4, addr);
                bh[2*p][0] = t4[0]; bh[2*p][1] = t4[1];
                bh[2*p+1][0] = t4[2]; bh[2*p+1][1] = t4[3];
                ldsm4(t4, addr + TILE_B);
                bl[2*p][0] = t4[0]; bl[2*p][1] = t4[1];
                bl[2*p+1][0] = t4[2]; bl[2*p+1][1] = t4[3];
            }
#pragma unroll
            for (int mi = 0; mi < 2; mi++)
#pragma unroll
                for (int ni = 0; ni < 8; ni++) {
                    mma_bf16(acc[mi][ni], ah[mi], bh[ni]);
                    mma_bf16(acc[mi][ni], ah[mi], bl[ni]);
                    mma_bf16(acc[mi][ni], al[mi], bh[ni]);
                }
        }
        __syncthreads();
    }

    // ---- epilogue ----
#pragma unroll
    for (int mi = 0; mi < 2; mi++) {
#pragma unroll
        for (int ni = 0; ni < 8; ni++) {
            const int row = m0 + (warp_m << 5) + (mi << 4) + (lane >> 2);
            const int col = n0 + (warp_n << 6) + (ni << 3) + ((lane & 3) << 1);
#pragma unroll
            for (int h = 0; h < 2; h++) {
                const size_t ro = (size_t)(row + h * 8) * ldc + col;
                float c0 = acc[mi][ni][2*h], c1 = acc[mi][ni][2*h + 1];
                if (MODE == 0) {
                    c0 = swishf(c0); c1 = swishf(c1);
                    *reinterpret_cast<float2*>(C + ro) = make_float2(c0, c1);
                } else if (MODE == 1) {
                    float ls0 = fminf(c0, 0.0f) - log1pf(expf(-fabsf(c0)));
                    float ls1 = fminf(c1, 0.0f) - log1pf(expf(-fabsf(c1)));
                    float g0 = ls0 * 0.125f, g1 = ls1 * 0.125f;
                    *reinterpret_cast<float2*>(C  + ro) = make_float2(g0, g1);
                    *reinterpret_cast<float2*>(C2 + ro) = make_float2(-expm1f(g0), -expm1f(g1));
                } else {
                    *reinterpret_cast<float2*>(C + ro) = make_float2(c0, c1);
                }
            }
        }
    }
}

// ---------------------------------------------------------------------------
// Sequential GSA scan. One CTA per (b,h). 256 threads. (unchanged, passing)
// ---------------------------------------------------------------------------
__global__ __launch_bounds__(256, 1)
void gsa_scan_kernel(const float* __restrict__ Q, const float* __restrict__ Kq,
                     const float* __restrict__ V, const float* __restrict__ S,
                     const float* __restrict__ G, float* __restrict__ O)
{
    const int bh   = blockIdx.x;
    const int b    = bh >> 3;
    const int h    = bh & 7;
    const int tid  = threadIdx.x;
    const int lane = tid & 31;
    const int w    = tid >> 5;

    __shared__ __align__(16) float sq[256], sk[256], sv[256];
    __shared__ __align__(16) float sdec[64], ssl[64], so1[64], sqv[64];

    const size_t qbase = (size_t)b * T_ * D_  + (size_t)h * DK_ + tid;
    const size_t fbase = (size_t)b * T_ * HM_ + (size_t)h * M_  + tid;

    float hk[8][8];
    float hv[64];
#pragma unroll
    for (int mi = 0; mi < 8; mi++)
#pragma unroll
        for (int di = 0; di < 8; di++) hk[mi][di] = 0.0f;
#pragma unroll
    for (int m = 0; m < 64; m++) hv[m] = 0.0f;

    float nq = Q[qbase], nk = Kq[qbase], nv = V[qbase];
    float nsv = 0.0f, ngv = 0.0f;
    if (tid < 64) { nsv = S[fbase]; ngv = G[fbase]; }

    for (int t = 0; t < T_; t++) {
        sq[tid] = nq; sk[tid] = nk; sv[tid] = nv;
        if (tid < 64) { ssl[tid] = nsv; sdec[tid] = expf(ngv); }
        __syncthreads();

        {
            const int tn_ = (t + 1 < T_) ? (t + 1) : t;
            nq = Q [qbase + (size_t)tn_ * D_];
            nk = Kq[qbase + (size_t)tn_ * D_];
            nv = V [qbase + (size_t)tn_ * D_];
            if (tid < 64) {
                nsv = S[fbase + (size_t)tn_ * HM_];
                ngv = G[fbase + (size_t)tn_ * HM_];
            }
        }

        float4 qa = *reinterpret_cast<const float4*>(&sq[lane * 8]);
        float4 qb = reinterpret_cast<const float4*>(&sq[lane * 8])[1];
        float4 ka = *reinterpret_cast<const float4*>(&sk[lane * 8]);
        float4 kb = reinterpret_cast<const float4*>(&sk[lane * 8])[1];
        float qr[8] = {qa.x, qa.y, qa.z, qa.w, qb.x, qb.y, qb.z, qb.w};
        float kr[8] = {ka.x, ka.y, ka.z, ka.w, kb.x, kb.y, kb.z, kb.w};

#pragma unroll
        for (int mi = 0; mi < 8; mi++) {
            const int m = w * 8 + mi;
            const float dm = sdec[m];
            const float sm = ssl[m];
            float p = 0.0f;
#pragma unroll
            for (int di = 0; di < 8; di++) {
                hk[mi][di] = hk[mi][di] * dm + kr[di] * sm;
                p += qr[di] * hk[mi][di];
            }
            p += __shfl_xor_sync(0xffffffffu, p, 16);
            p += __shfl_xor_sync(0xffffffffu, p, 8);
            p += __shfl_xor_sync(0xffffffffu, p, 4);
            p += __shfl_xor_sync(0xffffffffu, p, 2);
            p += __shfl_xor_sync(0xffffffffu, p, 1);
            if (lane == mi) so1[m] = p;
        }
        __syncthreads();

        if (w == 0) {
            float a = so1[lane], c = so1[lane + 32];
            float mx = fmaxf(a, c);
#pragma unroll
            for (int o = 16; o; o >>= 1) mx = fmaxf(mx, __shfl_xor_sync(0xffffffffu, mx, o));
            float ea = expf(a - mx), ec = expf(c - mx);
            float sm_ = ea + ec;
#pragma unroll
            for (int o = 16; o; o >>= 1) sm_ += __shfl_xor_sync(0xffffffffu, sm_, o);
            const float inv = 1.0f / sm_;
            sqv[lane]      = ea * inv;
            sqv[lane + 32] = ec * inv;
        }
        __syncthreads();

        const float vo = sv[tid];
        float acc = 0.0f;
#pragma unroll
        for (int m = 0; m < 64; m++) {
            hv[m] = hv[m] * sdec[m] + ssl[m] * vo;
            acc += sqv[m] * hv[m];
        }
        O[qbase + (size_t)t * D_] = acc;
        __syncthreads();
    }
}

// ---------------------------------------------------------------------------
// Host launcher
// ---------------------------------------------------------------------------
extern "C" void kernel_launch(void* const* d_in, const int* in_sizes, int n_in,
                              void* d_out, int out_size)
{
    (void)in_sizes; (void)n_in; (void)out_size;
    const float* hs       = (const float*)d_in[0];
    const float* norm_w   = (const float*)d_in[1];
    const float* q_w      = (const float*)d_in[2];
    const float* k_w      = (const float*)d_in[3];
    const float* v_w      = (const float*)d_in[4];
    const float* f_w      = (const float*)d_in[5];
    const float* g_norm_w = (const float*)d_in[6];
    const float* o_w      = (const float*)d_in[7];

    float *q, *k, *v, *gl, *sl, *o;
    cudaGetSymbolAddress((void**)&q,  g_q);
    cudaGetSymbolAddress((void**)&k,  g_k);
    cudaGetSymbolAddress((void**)&v,  g_v);
    cudaGetSymbolAddress((void**)&gl, g_gl);
    cudaGetSymbolAddress((void**)&sl, g_sl);
    cudaGetSymbolAddress((void**)&o,  g_o);

    __nv_bfloat16 *xh, *xl, *qwh, *qwl, *kwh, *kwl, *vwh, *vwl, *owh, *owl, *fwh, *fwl;
    cudaGetSymbolAddress((void**)&xh,  g_xh);
    cudaGetSymbolAddress((void**)&xl,  g_xl);
    cudaGetSymbolAddress((void**)&qwh, g_qwh);
    cudaGetSymbolAddress((void**)&qwl, g_qwl);
    cudaGetSymbolAddress((void**)&kwh, g_kwh);
    cudaGetSymbolAddress((void**)&kwl, g_kwl);
    cudaGetSymbolAddress((void**)&vwh, g_vwh);
    cudaGetSymbolAddress((void**)&vwl, g_vwl);
    cudaGetSymbolAddress((void**)&owh, g_owh);
    cudaGetSymbolAddress((void**)&owl, g_owl);
    cudaGetSymbolAddress((void**)&fwh, g_fwh);
    cudaGetSymbolAddress((void**)&fwl, g_fwl);

    static bool attr_done = false;
    if (!attr_done) {
        cudaFuncSetAttribute(bgemm_nt<0>, cudaFuncAttributeMaxDynamicSharedMemorySize, SMEM_B);
        cudaFuncSetAttribute(bgemm_nt<1>, cudaFuncAttributeMaxDynamicSharedMemorySize, SMEM_B);
        cudaFuncSetAttribute(bgemm_nt<2>, cudaFuncAttributeMaxDynamicSharedMemorySize, SMEM_B);
        attr_done = true;
    }

    // 0) split weights to bf16 hi/lo (deterministic each call)
    splitw_kernel<<<D_ * D_ / 1024, 256>>>(q_w, qwh, qwl);
    splitw_kernel<<<D_ * D_ / 1024, 256>>>(k_w, kwh, kwl);
    splitw_kernel<<<D_ * D_ / 1024, 256>>>(v_w, vwh, vwl);
    splitw_kernel<<<D_ * D_ / 1024, 256>>>(o_w, owh, owl);
    splitw_kernel<<<HM_ * D_ / 1024, 256>>>(f_w, fwh, fwl);

    // 1) x = rmsnorm(hidden_states) * norm_w, split to bf16 hi/lo
    rmsnorm_split_kernel<<<BT_, 256>>>(hs, norm_w, xh, xl);

    // 2) projections (tensor cores, split-bf16; fused activations)
    dim3 gqkv(D_ / 128, BT_ / 128);       // (16, 64)
    bgemm_nt<0><<<gqkv, 256, SMEM_B>>>(xh, xl, qwh, qwl, q, nullptr, D_, D_);
    bgemm_nt<0><<<gqkv, 256, SMEM_B>>>(xh, xl, kwh, kwl, k, nullptr, D_, D_);
    bgemm_nt<0><<<gqkv, 256, SMEM_B>>>(xh, xl, vwh, vwl, v, nullptr, D_, D_);
    dim3 gf(HM_ / 128, BT_ / 128);        // (4, 64)
    bgemm_nt<1><<<gf, 256, SMEM_B>>>(xh, xl, fwh, fwl, gl, sl, D_, HM_);

    // 3) sequential gated slot attention scan
    gsa_scan_kernel<<<B_ * H_, 256>>>(q, k, v, sl, gl, o);

    // 4) o = rmsnorm(swish(o)) * g_norm_w, split to bf16 hi/lo (reuse xh/xl)
    swishrms_split_kernel<<<BT_, 256>>>(o, g_norm_w, xh, xl);

    // 5) final projection -> d_out (fp32)
    bgemm_nt<2><<<gqkv, 256, SMEM_B>>>(xh, xl, owh, owl, (float*)d_out, nullptr, D_, D_);
}

// round 10
// speedup vs baseline: 2.5412x; 1.6451x over previous
#include <cuda_runtime.h>
#include <cuda_bf16.h>
#include <cstdint>

// Problem dims (fixed)
#define B_   4
#define T_   2048
#define D_   2048
#define H_   8
#define DK_  256
#define M_   64
#define HM_  512              // H_*M_
#define BT_  8192             // B_*T_
#define NC_  32               // chunks per sequence (T_/64)
#define NU_  1024             // total (bh, chunk) units

// ---------------------------------------------------------------------------
// Scratch (device globals; no allocation allowed)
// ---------------------------------------------------------------------------
__device__ float g_q [16777216];  // swish(q)       [BT, D]
__device__ float g_k [16777216];  // swish(k)       [BT, D]
__device__ float g_v [16777216];  // swish(v)       [BT, D]
__device__ float g_gl[ 4194304];  // log gates g    [BT, HM]
__device__ float g_sl[ 4194304];  // s = 1-exp(g)   [BT, HM]
__device__ float g_o [16777216];  // scan output    [BT, D]

// chunk-scan scratch: [unit=bh*32+c][16384]
__device__ float g_uk [16777216]; // Uk  [u][d*64+m]
__device__ float g_uv [16777216]; // Uv  [u][m*256+dv]
__device__ float g_hk0[16777216]; // Hk0 [u][d*64+m]
__device__ float g_hv0[16777216]; // Hv0 [u][m*256+dv]
__device__ float g_dec[   65536]; // exp(Gc) [u][64]

// bf16 split buffers
__device__ __nv_bfloat16 g_xh [16777216], g_xl [16777216];  // activations hi/lo
__device__ __nv_bfloat16 g_qwh[ 4194304], g_qwl[ 4194304];
__device__ __nv_bfloat16 g_kwh[ 4194304], g_kwl[ 4194304];
__device__ __nv_bfloat16 g_vwh[ 4194304], g_vwl[ 4194304];
__device__ __nv_bfloat16 g_owh[ 4194304], g_owl[ 4194304];
__device__ __nv_bfloat16 g_fwh[ 1048576], g_fwl[ 1048576];

__device__ __forceinline__ float swishf(float x) { return x / (1.0f + expf(-x)); }

__device__ __forceinline__ float f4c(float4 v, int i) {
    float r;
    switch (i) { case 0: r = v.x; break; case 1: r = v.y; break;
                 case 2: r = v.z; break; default: r = v.w; }
    return r;
}

// split fp32 -> (hi, lo) bf16
__device__ __forceinline__ void split1(float x, __nv_bfloat16& h, __nv_bfloat16& l)
{
    __nv_bfloat16 hh = __float2bfloat16(x);
    h = hh;
    l = __float2bfloat16(x - __bfloat162float(hh));
}

__device__ __forceinline__ void split4(float4 v, __nv_bfloat16* hp, __nv_bfloat16* lp)
{
    __nv_bfloat16 h0,h1,h2,h3,l0,l1,l2,l3;
    split1(v.x,h0,l0); split1(v.y,h1,l1); split1(v.z,h2,l2); split1(v.w,h3,l3);
    __nv_bfloat162* hp2 = reinterpret_cast<__nv_bfloat162*>(hp);
    __nv_bfloat162* lp2 = reinterpret_cast<__nv_bfloat162*>(lp);
    hp2[0] = __nv_bfloat162(h0,h1); hp2[1] = __nv_bfloat162(h2,h3);
    lp2[0] = __nv_bfloat162(l0,l1); lp2[1] = __nv_bfloat162(l2,l3);
}

// ---------------------------------------------------------------------------
// Weight splitter: fp32 -> bf16 hi/lo. 4 elems/thread.
// ---------------------------------------------------------------------------
__global__ __launch_bounds__(256)
void splitw_kernel(const float* __restrict__ x, __nv_bfloat16* __restrict__ h,
                   __nv_bfloat16* __restrict__ l)
{
    const int i = (blockIdx.x * 256 + threadIdx.x) * 4;
    float4 v = *reinterpret_cast<const float4*>(x + i);
    split4(v, h + i, l + i);
}

// ---------------------------------------------------------------------------
// RMSNorm over last dim (D=2048), output split bf16 hi/lo.
// ---------------------------------------------------------------------------
__global__ __launch_bounds__(256)
void rmsnorm_split_kernel(const float* __restrict__ x, const float* __restrict__ w,
                          __nv_bfloat16* __restrict__ yh, __nv_bfloat16* __restrict__ yl)
{
    const int row = blockIdx.x;
    const int t = threadIdx.x;
    const float4* xr = reinterpret_cast<const float4*>(x) + (size_t)row * (D_ / 4);
    float4 v0 = xr[t];
    float4 v1 = xr[t + 256];
    float ss = v0.x*v0.x + v0.y*v0.y + v0.z*v0.z + v0.w*v0.w
             + v1.x*v1.x + v1.y*v1.y + v1.z*v1.z + v1.w*v1.w;
#pragma unroll
    for (int o = 16; o; o >>= 1) ss += __shfl_xor_sync(0xffffffffu, ss, o);
    __shared__ float red[8];
    if ((t & 31) == 0) red[t >> 5] = ss;
    __syncthreads();
    float tot = red[0]+red[1]+red[2]+red[3]+red[4]+red[5]+red[6]+red[7];
    const float sc = rsqrtf(tot * (1.0f / (float)D_) + 1e-5f);
    const float4* wr = reinterpret_cast<const float4*>(w);
    float4 w0 = wr[t], w1 = wr[t + 256];
    float4 r0, r1;
    r0.x = v0.x * sc * w0.x;  r0.y = v0.y * sc * w0.y;
    r0.z = v0.z * sc * w0.z;  r0.w = v0.w * sc * w0.w;
    r1.x = v1.x * sc * w1.x;  r1.y = v1.y * sc * w1.y;
    r1.z = v1.z * sc * w1.z;  r1.w = v1.w * sc * w1.w;
    const size_t base = (size_t)row * D_;
    split4(r0, yh + base + t * 4,        yl + base + t * 4);
    split4(r1, yh + base + (t + 256)*4,  yl + base + (t + 256)*4);
}

// ---------------------------------------------------------------------------
// swish then RMSNorm, output split bf16 hi/lo.
// ---------------------------------------------------------------------------
__global__ __launch_bounds__(256)
void swishrms_split_kernel(const float* __restrict__ x, const float* __restrict__ w,
                           __nv_bfloat16* __restrict__ yh, __nv_bfloat16* __restrict__ yl)
{
    const int row = blockIdx.x;
    const int t = threadIdx.x;
    const float4* xr = reinterpret_cast<const float4*>(x) + (size_t)row * (D_ / 4);
    float4 v0 = xr[t];
    float4 v1 = xr[t + 256];
    v0.x = swishf(v0.x); v0.y = swishf(v0.y); v0.z = swishf(v0.z); v0.w = swishf(v0.w);
    v1.x = swishf(v1.x); v1.y = swishf(v1.y); v1.z = swishf(v1.z); v1.w = swishf(v1.w);
    float ss = v0.x*v0.x + v0.y*v0.y + v0.z*v0.z + v0.w*v0.w
             + v1.x*v1.x + v1.y*v1.y + v1.z*v1.z + v1.w*v1.w;
#pragma unroll
    for (int o = 16; o; o >>= 1) ss += __shfl_xor_sync(0xffffffffu, ss, o);
    __shared__ float red[8];
    if ((t & 31) == 0) red[t >> 5] = ss;
    __syncthreads();
    float tot = red[0]+red[1]+red[2]+red[3]+red[4]+red[5]+red[6]+red[7];
    const float sc = rsqrtf(tot * (1.0f / (float)D_) + 1e-5f);
    const float4* wr = reinterpret_cast<const float4*>(w);
    float4 w0 = wr[t], w1 = wr[t + 256];
    float4 r0, r1;
    r0.x = v0.x * sc * w0.x;  r0.y = v0.y * sc * w0.y;
    r0.z = v0.z * sc * w0.z;  r0.w = v0.w * sc * w0.w;
    r1.x = v1.x * sc * w1.x;  r1.y = v1.y * sc * w1.y;
    r1.z = v1.z * sc * w1.z;  r1.w = v1.w * sc * w1.w;
    const size_t base = (size_t)row * D_;
    split4(r0, yh + base + t * 4,        yl + base + t * 4);
    split4(r1, yh + base + (t + 256)*4,  yl + base + (t + 256)*4);
}

// ---------------------------------------------------------------------------
// PTX wrappers
// ---------------------------------------------------------------------------
__device__ __forceinline__ void mma_bf16(float* d, const uint32_t* a, const uint32_t* b)
{
    asm volatile(
        "mma.sync.aligned.m16n8k16.row.col.f32.bf16.bf16.f32 "
        "{%0,%1,%2,%3}, {%4,%5,%6,%7}, {%8,%9}, {%0,%1,%2,%3};"
        : "+f"(d[0]), "+f"(d[1]), "+f"(d[2]), "+f"(d[3])
        : "r"(a[0]), "r"(a[1]), "r"(a[2]), "r"(a[3]), "r"(b[0]), "r"(b[1]));
}

__device__ __forceinline__ void ldsm4(uint32_t* r, uint32_t addr)
{
    asm volatile("ldmatrix.sync.aligned.m8n8.x4.shared.b16 {%0,%1,%2,%3}, [%4];"
                 : "=r"(r[0]), "=r"(r[1]), "=r"(r[2]), "=r"(r[3]) : "r"(addr));
}

__device__ __forceinline__ void cp16(uint32_t dst, const void* src)
{
    asm volatile("cp.async.cg.shared.global [%0], [%1], 16;" :: "r"(dst), "l"(src));
}
__device__ __forceinline__ void cp_commit() { asm volatile("cp.async.commit_group;"); }
template<int N> __device__ __forceinline__ void cp_wait()
{ asm volatile("cp.async.wait_group %0;" :: "n"(N)); }

// ---------------------------------------------------------------------------
// Split-bf16 GEMM (NT) — unchanged from R7 (passing).
// ---------------------------------------------------------------------------
#define TILE_B   10240            // one 128x40 bf16 tile in bytes
#define STAGE_B  (4 * TILE_B)     // Ah, Al, Bh, Bl
#define SMEM_B   (2 * STAGE_B)    // double buffered (81920 B)

template<int MODE>
__global__ __launch_bounds__(256, 1)
void bgemm_nt(const __nv_bfloat16* __restrict__ Ah, const __nv_bfloat16* __restrict__ Al,
              const __nv_bfloat16* __restrict__ Bh, const __nv_bfloat16* __restrict__ Bl,
              float* __restrict__ C, float* __restrict__ C2,
              const int K, const int ldc)
{
    extern __shared__ __align__(16) char smem_raw[];
    const uint32_t sbase = (uint32_t)__cvta_generic_to_shared(smem_raw);

    const int tid    = threadIdx.x;
    const int lane   = tid & 31;
    const int warp   = tid >> 5;
    const int warp_m = warp >> 1;
    const int warp_n = warp & 1;
    const int m0     = blockIdx.y * 128;
    const int n0     = blockIdx.x * 128;

    float acc[2][8][4];
#pragma unroll
    for (int mi = 0; mi < 2; mi++)
#pragma unroll
        for (int ni = 0; ni < 8; ni++)
#pragma unroll
            for (int e = 0; e < 4; e++) acc[mi][ni][e] = 0.0f;

    auto load_stage = [&](int s, int kt) {
        const uint32_t sb = sbase + s * STAGE_B;
        const int k0 = kt * 32;
#pragma unroll
        for (int i = 0; i < 2; i++) {
            const int c   = tid + (i << 8);
            const int row = c >> 2;
            const int kc  = (c & 3) << 3;
            const uint32_t doff = sb + (uint32_t)(row * 40 + kc) * 2;
            const size_t gA = (size_t)(m0 + row) * K + k0 + kc;
            const size_t gB = (size_t)(n0 + row) * K + k0 + kc;
            cp16(doff,               Ah + gA);
            cp16(doff + TILE_B,      Al + gA);
            cp16(doff + 2 * TILE_B,  Bh + gB);
            cp16(doff + 3 * TILE_B,  Bl + gB);
        }
    };

    load_stage(0, 0);
    cp_commit();

    const int nkt = K >> 5;
    const int r = lane & 7;
    const int g = lane >> 3;
    const int a_row_off = ((g & 1) << 3) + r;
    const int a_k_off   = (g >> 1) << 3;
    const int b_row_off = ((g >> 1) << 3) + r;
    const int b_k_off   = (g & 1) << 3;

    for (int kt = 0; kt < nkt; kt++) {
        if (kt + 1 < nkt) { load_stage((kt + 1) & 1, kt + 1); cp_commit(); cp_wait<1>(); }
        else              { cp_wait<0>(); }
        __syncthreads();

        const uint32_t sA = sbase + (kt & 1) * STAGE_B;
        const uint32_t sB = sA + 2 * TILE_B;

#pragma unroll
        for (int kk = 0; kk < 32; kk += 16) {
            uint32_t ah[2][4], al[2][4], bh[8][2], bl[8][2];
#pragma unroll
            for (int mi = 0; mi < 2; mi++) {
                const uint32_t addr = sA +
                    (uint32_t)(((warp_m << 5) + (mi << 4) + a_row_off) * 40 + kk + a_k_off) * 2;
                ldsm4(ah[mi], addr);
                ldsm4(al[mi], addr + TILE_B);
            }
#pragma unroll
            for (int p = 0; p < 4; p++) {
                const uint32_t addr = sB +
                    (uint32_t)(((warp_n << 6) + (p << 4) + b_row_off) * 40 + kk + b_k_off) * 2;
                uint32_t t4[4];
                ldsm4(t4, addr);
                bh[2*p][0] = t4[0]; bh[2*p][1] = t4[1];
                bh[2*p+1][0] = t4[2]; bh[2*p+1][1] = t4[3];
                ldsm4(t4, addr + TILE_B);
                bl[2*p][0] = t4[0]; bl[2*p][1] = t4[1];
                bl[2*p+1][0] = t4[2]; bl[2*p+1][1] = t4[3];
            }
#pragma unroll
            for (int mi = 0; mi < 2; mi++)
#pragma unroll
                for (int ni = 0; ni < 8; ni++) {
                    mma_bf16(acc[mi][ni], ah[mi], bh[ni]);
                    mma_bf16(acc[mi][ni], ah[mi], bl[ni]);
                    mma_bf16(acc[mi][ni], al[mi], bh[ni]);
                }
        }
        __syncthreads();
    }

#pragma unroll
    for (int mi = 0; mi < 2; mi++) {
#pragma unroll
        for (int ni = 0; ni < 8; ni++) {
            const int row = m0 + (warp_m << 5) + (mi << 4) + (lane >> 2);
            const int col = n0 + (warp_n << 6) + (ni << 3) + ((lane & 3) << 1);
#pragma unroll
            for (int h = 0; h < 2; h++) {
                const size_t ro = (size_t)(row + h * 8) * ldc + col;
                float c0 = acc[mi][ni][2*h], c1 = acc[mi][ni][2*h + 1];
                if (MODE == 0) {
                    c0 = swishf(c0); c1 = swishf(c1);
                    *reinterpret_cast<float2*>(C + ro) = make_float2(c0, c1);
                } else if (MODE == 1) {
                    float ls0 = fminf(c0, 0.0f) - log1pf(expf(-fabsf(c0)));
                    float ls1 = fminf(c1, 0.0f) - log1pf(expf(-fabsf(c1)));
                    float g0 = ls0 * 0.125f, g1 = ls1 * 0.125f;
                    *reinterpret_cast<float2*>(C  + ro) = make_float2(g0, g1);
                    *reinterpret_cast<float2*>(C2 + ro) = make_float2(-expm1f(g0), -expm1f(g1));
                } else {
                    *reinterpret_cast<float2*>(C + ro) = make_float2(c0, c1);
                }
            }
        }
    }
}

// ===========================================================================
// Chunked GSA scan — 3 phases, chunk length 64.
// unit = bh*32 + c;  bh = b*8 + h.
// Math: G_t = cumsum(g) within chunk; e_t = exp(G_t); a_j = exp(-G_j)*s_j;
//   W_j = exp(Gc - G_j)*s_j;  Uk = K^T W;  Uv = W^T V;
//   Hk0/Hv0 = inter-chunk states (phase B scan over Uk/Uv with dec=exp(Gc));
//   o1 = e_t * (Q Hk0 + tril(Q K^T) A);  qv = softmax_m(o1);  qe = qv*e_t;
//   o  = qe Hv0 + tril(qe A^T) V.
// ===========================================================================

#define SMEM_A_BYTES (65536 + 2 * 64 * 68 * 4)          // 100352
#define SMEM_C_BYTES (2 * 65536 + 4 * 64 * 68 * 4)      // 200704

__global__ __launch_bounds__(256, 1)
void gsa_phaseA(const float* __restrict__ Kx, const float* __restrict__ Vx,
                const float* __restrict__ S, const float* __restrict__ G,
                float* __restrict__ Uk, float* __restrict__ Uv,
                float* __restrict__ Dec)
{
    extern __shared__ float sm[];
    float* sKV = sm;                 // 64 x 256
    float* sG  = sm + 16384;         // 64 x 68 (g)
    float* sW  = sG + 64 * 68;       // 64 x 68 (s -> W)

    const int unit = blockIdx.x;
    const int c = unit & 31, bh = unit >> 5;
    const int b = bh >> 3, h = bh & 7;
    const int tid = threadIdx.x;
    const size_t rbase = ((size_t)b * T_ + (size_t)c * 64) * D_  + (size_t)h * 256;
    const size_t fbase = ((size_t)b * T_ + (size_t)c * 64) * HM_ + (size_t)h * 64;
    const size_t ubase = (size_t)unit * 16384;

    // load K chunk + g/s chunk
#pragma unroll
    for (int i = 0; i < 16; i++) {
        const int idx = (tid + i * 256) * 4;
        const int t = idx >> 8, d = idx & 255;
        *reinterpret_cast<float4*>(&sKV[idx]) =
            *reinterpret_cast<const float4*>(&Kx[rbase + (size_t)t * D_ + d]);
    }
#pragma unroll
    for (int i = 0; i < 4; i++) {
        const int idx = (tid + i * 256) * 4;
        const int t = idx >> 6, m = idx & 63;
        *reinterpret_cast<float4*>(&sG[t * 68 + m]) =
            *reinterpret_cast<const float4*>(&G[fbase + (size_t)t * HM_ + m]);
        *reinterpret_cast<float4*>(&sW[t * 68 + m]) =
            *reinterpret_cast<const float4*>(&S[fbase + (size_t)t * HM_ + m]);
    }
    __syncthreads();

    if (tid < 64) {
        const int m = tid;
        float Gc = 0.0f;
        for (int t = 0; t < 64; t++) Gc += sG[t * 68 + m];
        Dec[(size_t)unit * 64 + m] = expf(Gc);
        float Gr = 0.0f;
        for (int t = 0; t < 64; t++) {
            Gr += sG[t * 68 + m];
            sW[t * 68 + m] = expf(Gc - Gr) * sW[t * 68 + m];
        }
    }
    __syncthreads();

    // Uk[d][m] = sum_j K[j][d] * W[j][m]
    {
        const int d0 = (tid >> 2) * 4;
        const int m0 = (tid & 3) * 16;
        float acc[4][16];
#pragma unroll
        for (int i = 0; i < 4; i++)
#pragma unroll
            for (int j = 0; j < 16; j++) acc[i][j] = 0.0f;
        for (int j = 0; j < 64; j++) {
            const float4 k4 = *reinterpret_cast<const float4*>(&sKV[j * 256 + d0]);
            float w[16];
#pragma unroll
            for (int q4 = 0; q4 < 4; q4++) {
                const float4 w4 = *reinterpret_cast<const float4*>(&sW[j * 68 + m0 + q4 * 4]);
                w[q4*4+0] = w4.x; w[q4*4+1] = w4.y; w[q4*4+2] = w4.z; w[q4*4+3] = w4.w;
            }
#pragma unroll
            for (int di = 0; di < 4; di++) {
                const float kv = f4c(k4, di);
#pragma unroll
                for (int mi = 0; mi < 16; mi++) acc[di][mi] += kv * w[mi];
            }
        }
#pragma unroll
        for (int di = 0; di < 4; di++)
#pragma unroll
            for (int q4 = 0; q4 < 4; q4++)
                *reinterpret_cast<float4*>(&Uk[ubase + (size_t)(d0 + di) * 64 + m0 + q4 * 4]) =
                    make_float4(acc[di][q4*4], acc[di][q4*4+1], acc[di][q4*4+2], acc[di][q4*4+3]);
    }
    __syncthreads();

    // load V chunk
#pragma unroll
    for (int i = 0; i < 16; i++) {
        const int idx = (tid + i * 256) * 4;
        const int t = idx >> 8, d = idx & 255;
        *reinterpret_cast<float4*>(&sKV[idx]) =
            *reinterpret_cast<const float4*>(&Vx[rbase + (size_t)t * D_ + d]);
    }
    __syncthreads();

    // Uv[m][dv] = sum_j W[j][m] * V[j][dv]
    {
        const int m0 = (tid >> 4) * 4;
        const int v0 = (tid & 15) * 16;
        float acc[4][16];
#pragma unroll
        for (int i = 0; i < 4; i++)
#pragma unroll
            for (int j = 0; j < 16; j++) acc[i][j] = 0.0f;
        for (int j = 0; j < 64; j++) {
            const float4 w4 = *reinterpret_cast<const float4*>(&sW[j * 68 + m0]);
            float v[16];
#pragma unroll
            for (int q4 = 0; q4 < 4; q4++) {
                const float4 v4 = *reinterpret_cast<const float4*>(&sKV[j * 256 + v0 + q4 * 4]);
                v[q4*4+0] = v4.x; v[q4*4+1] = v4.y; v[q4*4+2] = v4.z; v[q4*4+3] = v4.w;
            }
#pragma unroll
            for (int mi = 0; mi < 4; mi++) {
                const float wv = f4c(w4, mi);
#pragma unroll
                for (int vi = 0; vi < 16; vi++) acc[mi][vi] += wv * v[vi];
            }
        }
#pragma unroll
        for (int mi = 0; mi < 4; mi++)
#pragma unroll
            for (int q4 = 0; q4 < 4; q4++)
                *reinterpret_cast<float4*>(&Uv[ubase + (size_t)(m0 + mi) * 256 + v0 + q4 * 4]) =
                    make_float4(acc[mi][q4*4], acc[mi][q4*4+1], acc[mi][q4*4+2], acc[mi][q4*4+3]);
    }
}

__global__ __launch_bounds__(256, 1)
void gsa_phaseB(const float* __restrict__ Uk, const float* __restrict__ Uv,
                const float* __restrict__ Dec,
                float* __restrict__ Hk0, float* __restrict__ Hv0)
{
    const int bh = blockIdx.x;
    const int tid = threadIdx.x;
    __shared__ float sdec[64];

    float hk[64], hv[64];
#pragma unroll
    for (int m = 0; m < 64; m++) { hk[m] = 0.0f; hv[m] = 0.0f; }

    for (int c = 0; c < NC_; c++) {
        const size_t u = ((size_t)bh * NC_ + c) * 16384;
        // store pre-chunk state
#pragma unroll
        for (int m = 0; m < 64; m += 4)
            *reinterpret_cast<float4*>(&Hk0[u + (size_t)tid * 64 + m]) =
                make_float4(hk[m], hk[m+1], hk[m+2], hk[m+3]);
#pragma unroll
        for (int m = 0; m < 64; m++)
            Hv0[u + (size_t)m * 256 + tid] = hv[m];
        __syncthreads();
        if (tid < 64) sdec[tid] = Dec[((size_t)bh * NC_ + c) * 64 + tid];
        __syncthreads();
#pragma unroll
        for (int m = 0; m < 64; m += 4) {
            const float4 u4 = *reinterpret_cast<const float4*>(&Uk[u + (size_t)tid * 64 + m]);
            hk[m+0] = hk[m+0] * sdec[m+0] + u4.x;
            hk[m+1] = hk[m+1] * sdec[m+1] + u4.y;
            hk[m+2] = hk[m+2] * sdec[m+2] + u4.z;
            hk[m+3] = hk[m+3] * sdec[m+3] + u4.w;
        }
#pragma unroll
        for (int m = 0; m < 64; m++)
            hv[m] = hv[m] * sdec[m] + Uv[u + (size_t)m * 256 + tid];
        __syncthreads();
    }
}

__global__ __launch_bounds__(256, 1)
void gsa_phaseC(const float* __restrict__ Qx, const float* __restrict__ Kx,
                const float* __restrict__ Vx, const float* __restrict__ S,
                const float* __restrict__ G,
                const float* __restrict__ Hk0, const float* __restrict__ Hv0,
                float* __restrict__ O)
{
    extern __shared__ float sm[];
    float* sQ  = sm;                  // 64 x 256
    float* sKV = sm + 16384;          // 64 x 256 (K -> Hk0 -> Hv0 -> V)
    float* sA  = sm + 32768;          // 64 x 68  (s -> a)
    float* sS1 = sA  + 64 * 68;       // 64 x 68  (S1 -> R)
    float* sP  = sS1 + 64 * 68;       // 64 x 68  (o1 -> qv -> qe)
    float* sE  = sP  + 64 * 68;       // 64 x 68  (g -> e)

    const int unit = blockIdx.x;
    const int c = unit & 31, bh = unit >> 5;
    const int b = bh >> 3, h = bh & 7;
    const int tid = threadIdx.x;
    const size_t rbase = ((size_t)b * T_ + (size_t)c * 64) * D_  + (size_t)h * 256;
    const size_t fbase = ((size_t)b * T_ + (size_t)c * 64) * HM_ + (size_t)h * 64;
    const size_t ubase = (size_t)unit * 16384;

    // load Q, K, g, s
#pragma unroll
    for (int i = 0; i < 16; i++) {
        const int idx = (tid + i * 256) * 4;
        const int t = idx >> 8, d = idx & 255;
        *reinterpret_cast<float4*>(&sQ[idx]) =
            *reinterpret_cast<const float4*>(&Qx[rbase + (size_t)t * D_ + d]);
        *reinterpret_cast<float4*>(&sKV[idx]) =
            *reinterpret_cast<const float4*>(&Kx[rbase + (size_t)t * D_ + d]);
    }
#pragma unroll
    for (int i = 0; i < 4; i++) {
        const int idx = (tid + i * 256) * 4;
        const int t = idx >> 6, m = idx & 63;
        *reinterpret_cast<float4*>(&sE[t * 68 + m]) =
            *reinterpret_cast<const float4*>(&G[fbase + (size_t)t * HM_ + m]);
        *reinterpret_cast<float4*>(&sA[t * 68 + m]) =
            *reinterpret_cast<const float4*>(&S[fbase + (size_t)t * HM_ + m]);
    }
    __syncthreads();

    // prefix: e_t = exp(G_t), a_t = exp(-G_t)*s_t
    if (tid < 64) {
        const int m = tid;
        float Gr = 0.0f;
        for (int t = 0; t < 64; t++) {
            Gr += sE[t * 68 + m];
            sE[t * 68 + m] = expf(Gr);
            sA[t * 68 + m] = expf(-Gr) * sA[t * 68 + m];
        }
    }
    __syncthreads();

    const int t0 = (tid >> 4) << 2;
    const int x0 = (tid & 15) << 2;
    const int v0 = (tid & 15) << 4;

    // (a) S1 = tril(Q K^T)
    {
        float acc[4][4];
#pragma unroll
        for (int i = 0; i < 4; i++)
#pragma unroll
            for (int j = 0; j < 4; j++) acc[i][j] = 0.0f;
        for (int d = 0; d < 256; d += 4) {
            float4 q4[4], k4[4];
#pragma unroll
            for (int i = 0; i < 4; i++)
                q4[i] = *reinterpret_cast<const float4*>(&sQ[(t0 + i) * 256 + d]);
#pragma unroll
            for (int j = 0; j < 4; j++)
                k4[j] = *reinterpret_cast<const float4*>(&sKV[(x0 + j) * 256 + d]);
#pragma unroll
            for (int i = 0; i < 4; i++)
#pragma unroll
                for (int j = 0; j < 4; j++)
                    acc[i][j] += q4[i].x * k4[j].x + q4[i].y * k4[j].y
                               + q4[i].z * k4[j].z + q4[i].w * k4[j].w;
        }
#pragma unroll
        for (int i = 0; i < 4; i++)
#pragma unroll
            for (int j = 0; j < 4; j++)
                sS1[(t0 + i) * 68 + x0 + j] = (x0 + j <= t0 + i) ? acc[i][j] : 0.0f;
    }
    __syncthreads();

    // load Hk0 into sKV
#pragma unroll
    for (int i = 0; i < 16; i++) {
        const int idx = (tid + i * 256) * 4;
        *reinterpret_cast<float4*>(&sKV[idx]) =
            *reinterpret_cast<const float4*>(&Hk0[ubase + idx]);
    }
    __syncthreads();

    // o1 = E * (S1*A + Q*Hk0)
    {
        float acc[4][4];
#pragma unroll
        for (int i = 0; i < 4; i++)
#pragma unroll
            for (int j = 0; j < 4; j++) acc[i][j] = 0.0f;
        for (int j = 0; j < 64; j += 4) {
            float4 s4[4];
#pragma unroll
            for (int i = 0; i < 4; i++)
                s4[i] = *reinterpret_cast<const float4*>(&sS1[(t0 + i) * 68 + j]);
#pragma unroll
            for (int jj = 0; jj < 4; jj++) {
                const float4 a4 = *reinterpret_cast<const float4*>(&sA[(j + jj) * 68 + x0]);
#pragma unroll
                for (int i = 0; i < 4; i++) {
                    const float sv = f4c(s4[i], jj);
                    acc[i][0] += sv * a4.x; acc[i][1] += sv * a4.y;
                    acc[i][2] += sv * a4.z; acc[i][3] += sv * a4.w;
                }
            }
        }
        for (int d = 0; d < 256; d += 4) {
            float4 q4[4];
#pragma unroll
            for (int i = 0; i < 4; i++)
                q4[i] = *reinterpret_cast<const float4*>(&sQ[(t0 + i) * 256 + d]);
#pragma unroll
            for (int dd = 0; dd < 4; dd++) {
                const float4 h4 = *reinterpret_cast<const float4*>(&sKV[(d + dd) * 64 + x0]);
#pragma unroll
                for (int i = 0; i < 4; i++) {
                    const float qv = f4c(q4[i], dd);
                    acc[i][0] += qv * h4.x; acc[i][1] += qv * h4.y;
                    acc[i][2] += qv * h4.z; acc[i][3] += qv * h4.w;
                }
            }
        }
#pragma unroll
        for (int i = 0; i < 4; i++)
#pragma unroll
            for (int j = 0; j < 4; j++)
                sP[(t0 + i) * 68 + x0 + j] = sE[(t0 + i) * 68 + x0 + j] * acc[i][j];
    }
    __syncthreads();

    // load Hv0 into sKV (safe: sKV last read before previous sync)
#pragma unroll
    for (int i = 0; i < 16; i++) {
        const int idx = (tid + i * 256) * 4;
        *reinterpret_cast<float4*>(&sKV[idx]) =
            *reinterpret_cast<const float4*>(&Hv0[ubase + idx]);
    }
    // softmax over m, then qe = qv * e
    if (tid < 64) {
        const int t = tid;
        float mx = -1e30f;
        for (int m = 0; m < 64; m++) mx = fmaxf(mx, sP[t * 68 + m]);
        float sum = 0.0f;
        for (int m = 0; m < 64; m++) {
            const float e_ = expf(sP[t * 68 + m] - mx);
            sP[t * 68 + m] = e_;
            sum += e_;
        }
        const float inv = 1.0f / sum;
        for (int m = 0; m < 64; m++)
            sP[t * 68 + m] = sP[t * 68 + m] * inv * sE[t * 68 + m];
    }
    __syncthreads();

    // inter2 = qe * Hv0  (accumulators kept live)
    float accO[4][16];
#pragma unroll
    for (int i = 0; i < 4; i++)
#pragma unroll
        for (int j = 0; j < 16; j++) accO[i][j] = 0.0f;
    for (int m = 0; m < 64; m += 4) {
        float4 qe4[4];
#pragma unroll
        for (int i = 0; i < 4; i++)
            qe4[i] = *reinterpret_cast<const float4*>(&sP[(t0 + i) * 68 + m]);
#pragma unroll
        for (int mm = 0; mm < 4; mm++) {
            float hvv[16];
#pragma unroll
            for (int q4 = 0; q4 < 4; q4++) {
                const float4 h4 = *reinterpret_cast<const float4*>(&sKV[(m + mm) * 256 + v0 + q4 * 4]);
                hvv[q4*4+0] = h4.x; hvv[q4*4+1] = h4.y; hvv[q4*4+2] = h4.z; hvv[q4*4+3] = h4.w;
            }
#pragma unroll
            for (int i = 0; i < 4; i++) {
                const float qv = f4c(qe4[i], mm);
#pragma unroll
                for (int vi = 0; vi < 16; vi++) accO[i][vi] += qv * hvv[vi];
            }
        }
    }

    // R = tril(qe * A^T) -> sS1
    {
        float acc[4][4];
#pragma unroll
        for (int i = 0; i < 4; i++)
#pragma unroll
            for (int j = 0; j < 4; j++) acc[i][j] = 0.0f;
        for (int m = 0; m < 64; m += 4) {
            float4 qe4[4], a4[4];
#pragma unroll
            for (int i = 0; i < 4; i++)
                qe4[i] = *reinterpret_cast<const float4*>(&sP[(t0 + i) * 68 + m]);
#pragma unroll
            for (int j = 0; j < 4; j++)
                a4[j] = *reinterpret_cast<const float4*>(&sA[(x0 + j) * 68 + m]);
#pragma unroll
            for (int i = 0; i < 4; i++)
#pragma unroll
                for (int j = 0; j < 4; j++)
                    acc[i][j] += qe4[i].x * a4[j].x + qe4[i].y * a4[j].y
                               + qe4[i].z * a4[j].z + qe4[i].w * a4[j].w;
        }
#pragma unroll
        for (int i = 0; i < 4; i++)
#pragma unroll
            for (int j = 0; j < 4; j++)
                sS1[(t0 + i) * 68 + x0 + j] = (x0 + j <= t0 + i) ? acc[i][j] : 0.0f;
    }
    __syncthreads();

    // load V into sKV
#pragma unroll
    for (int i = 0; i < 16; i++) {
        const int idx = (tid + i * 256) * 4;
        const int t = idx >> 8, d = idx & 255;
        *reinterpret_cast<float4*>(&sKV[idx]) =
            *reinterpret_cast<const float4*>(&Vx[rbase + (size_t)t * D_ + d]);
    }
    __syncthreads();

    // o = inter2 + R * V, write out
    for (int j = 0; j < 64; j += 4) {
        float4 r4[4];
#pragma unroll
        for (int i = 0; i < 4; i++)
            r4[i] = *reinterpret_cast<const float4*>(&sS1[(t0 + i) * 68 + j]);
#pragma unroll
        for (int jj = 0; jj < 4; jj++) {
            float vv[16];
#pragma unroll
            for (int q4 = 0; q4 < 4; q4++) {
                const float4 v4 = *reinterpret_cast<const float4*>(&sKV[(j + jj) * 256 + v0 + q4 * 4]);
                vv[q4*4+0] = v4.x; vv[q4*4+1] = v4.y; vv[q4*4+2] = v4.z; vv[q4*4+3] = v4.w;
            }
#pragma unroll
            for (int i = 0; i < 4; i++) {
                const float rv = f4c(r4[i], jj);
#pragma unroll
                for (int vi = 0; vi < 16; vi++) accO[i][vi] += rv * vv[vi];
            }
        }
    }
#pragma unroll
    for (int i = 0; i < 4; i++)
#pragma unroll
        for (int q4 = 0; q4 < 4; q4++)
            *reinterpret_cast<float4*>(&O[rbase + (size_t)(t0 + i) * D_ + v0 + q4 * 4]) =
                make_float4(accO[i][q4*4], accO[i][q4*4+1], accO[i][q4*4+2], accO[i][q4*4+3]);
}

// ---------------------------------------------------------------------------
// Host launcher
// ---------------------------------------------------------------------------
extern "C" void kernel_launch(void* const* d_in, const int* in_sizes, int n_in,
                              void* d_out, int out_size)
{
    (void)in_sizes; (void)n_in; (void)out_size;
    const float* hs       = (const float*)d_in[0];
    const float* norm_w   = (const float*)d_in[1];
    const float* q_w      = (const float*)d_in[2];
    const float* k_w      = (const float*)d_in[3];
    const float* v_w      = (const float*)d_in[4];
    const float* f_w      = (const float*)d_in[5];
    const float* g_norm_w = (const float*)d_in[6];
    const float* o_w      = (const float*)d_in[7];

    float *q, *k, *v, *gl, *sl, *o, *uk, *uv, *hk0, *hv0, *dec;
    cudaGetSymbolAddress((void**)&q,   g_q);
    cudaGetSymbolAddress((void**)&k,   g_k);
    cudaGetSymbolAddress((void**)&v,   g_v);
    cudaGetSymbolAddress((void**)&gl,  g_gl);
    cudaGetSymbolAddress((void**)&sl,  g_sl);
    cudaGetSymbolAddress((void**)&o,   g_o);
    cudaGetSymbolAddress((void**)&uk,  g_uk);
    cudaGetSymbolAddress((void**)&uv,  g_uv);
    cudaGetSymbolAddress((void**)&hk0, g_hk0);
    cudaGetSymbolAddress((void**)&hv0, g_hv0);
    cudaGetSymbolAddress((void**)&dec, g_dec);

    __nv_bfloat16 *xh, *xl, *qwh, *qwl, *kwh, *kwl, *vwh, *vwl, *owh, *owl, *fwh, *fwl;
    cudaGetSymbolAddress((void**)&xh,  g_xh);
    cudaGetSymbolAddress((void**)&xl,  g_xl);
    cudaGetSymbolAddress((void**)&qwh, g_qwh);
    cudaGetSymbolAddress((void**)&qwl, g_qwl);
    cudaGetSymbolAddress((void**)&kwh, g_kwh);
    cudaGetSymbolAddress((void**)&kwl, g_kwl);
    cudaGetSymbolAddress((void**)&vwh, g_vwh);
    cudaGetSymbolAddress((void**)&vwl, g_vwl);
    cudaGetSymbolAddress((void**)&owh, g_owh);
    cudaGetSymbolAddress((void**)&owl, g_owl);
    cudaGetSymbolAddress((void**)&fwh, g_fwh);
    cudaGetSymbolAddress((void**)&fwl, g_fwl);

    static bool attr_done = false;
    if (!attr_done) {
        cudaFuncSetAttribute(bgemm_nt<0>, cudaFuncAttributeMaxDynamicSharedMemorySize, SMEM_B);
        cudaFuncSetAttribute(bgemm_nt<1>, cudaFuncAttributeMaxDynamicSharedMemorySize, SMEM_B);
        cudaFuncSetAttribute(bgemm_nt<2>, cudaFuncAttributeMaxDynamicSharedMemorySize, SMEM_B);
        cudaFuncSetAttribute(gsa_phaseA, cudaFuncAttributeMaxDynamicSharedMemorySize, SMEM_A_BYTES);
        cudaFuncSetAttribute(gsa_phaseC, cudaFuncAttributeMaxDynamicSharedMemorySize, SMEM_C_BYTES);
        attr_done = true;
    }

    // 0) split weights to bf16 hi/lo
    splitw_kernel<<<D_ * D_ / 1024, 256>>>(q_w, qwh, qwl);
    splitw_kernel<<<D_ * D_ / 1024, 256>>>(k_w, kwh, kwl);
    splitw_kernel<<<D_ * D_ / 1024, 256>>>(v_w, vwh, vwl);
    splitw_kernel<<<D_ * D_ / 1024, 256>>>(o_w, owh, owl);
    splitw_kernel<<<HM_ * D_ / 1024, 256>>>(f_w, fwh, fwl);

    // 1) x = rmsnorm(hidden_states) * norm_w, split to bf16 hi/lo
    rmsnorm_split_kernel<<<BT_, 256>>>(hs, norm_w, xh, xl);

    // 2) projections
    dim3 gqkv(D_ / 128, BT_ / 128);
    bgemm_nt<0><<<gqkv, 256, SMEM_B>>>(xh, xl, qwh, qwl, q, nullptr, D_, D_);
    bgemm_nt<0><<<gqkv, 256, SMEM_B>>>(xh, xl, kwh, kwl, k, nullptr, D_, D_);
    bgemm_nt<0><<<gqkv, 256, SMEM_B>>>(xh, xl, vwh, vwl, v, nullptr, D_, D_);
    dim3 gf(HM_ / 128, BT_ / 128);
    bgemm_nt<1><<<gf, 256, SMEM_B>>>(xh, xl, fwh, fwl, gl, sl, D_, HM_);

    // 3) chunked GSA scan
    gsa_phaseA<<<NU_, 256, SMEM_A_BYTES>>>(k, v, sl, gl, uk, uv, dec);
    gsa_phaseB<<<B_ * H_, 256>>>(uk, uv, dec, hk0, hv0);
    gsa_phaseC<<<NU_, 256, SMEM_C_BYTES>>>(q, k, v, sl, gl, hk0, hv0, o);

    // 4) o = rmsnorm(swish(o)) * g_norm_w
    swishrms_split_kernel<<<BT_, 256>>>(o, g_norm_w, xh, xl);

    // 5) final projection -> d_out (fp32)
    bgemm_nt<2><<<gqkv, 256, SMEM_B>>>(xh, xl, owh, owl, (float*)d_out, nullptr, D_, D_);
}